// round 16
// baseline (speedup 1.0000x reference)
#include <cuda_runtime.h>
#include <cuda_fp16.h>
#include <cstdint>
#include <math.h>

// ============================================================================
// Fused NeRF MLP (RadianceField), base sm_100 target (no tcgen05).
// fp16 mma.sync.m16n8k16 (fp32 accum) + ldmatrix.x4, persistent 256-thread
// CTAs, weights pre-converted to fp16 and streamed in 128-k chunks through a
// 2-slot cp.async ring (lookahead 1), fp16 activations in SMEM.
// R16: stmatrix.x2 epilogue; next-tile x staged by idle warps during rgb head.
// ============================================================================

#define NTHREADS 256
#define MTILE    128

// SMEM map (bytes)
#define ACT_OFF  0                     // 128 rows x 512B (256 half cols), swizzled
#define XB_OFF   65536                 // 128 rows x 256B (128 half cols), swizzled
#define WB_OFF   98304                 // 2 x 65536 weight chunk ring
#define WB_BYTES 65536                 // slot: 256 rows x 256B
#define SMEM_TOTAL (WB_OFF + 2 * WB_BYTES)   // 229376 <= 232448 cap

#define NCHUNKS  24
#define WH_TOTAL 647168

struct Params { const float* p[32]; };

__constant__ int c_widx[13] = {2, 4, 6, 8, 10, 12, 14, 16, 20, 22, 24, 26, 28};
__constant__ int c_kact[13] = {63, 256, 256, 256, 256, 319, 256, 256, 256, 283, 128, 128, 128};
__constant__ int c_kpad[13] = {64, 256, 256, 256, 256, 320, 256, 256, 256, 320, 128, 128, 128};
__constant__ int c_nch [13] = { 1,   2,   2,   2,   2,   3,   2,   2,   2,   3,   1,   1,   1};
__constant__ int c_woff[13] = {0, 16384, 81920, 147456, 212992, 278528, 360448,
                               425984, 491520, 557056, 598016, 614400, 630784};
// flat chunk tables
__constant__ int ck_li[NCHUNKS] = {0, 1,1, 2,2, 3,3, 4,4, 5,5,5, 6,6, 7,7, 8,8, 9,9,9, 10, 11, 12};
__constant__ int ck_c [NCHUNKS] = {0, 0,1, 0,1, 0,1, 0,1, 0,1,2, 0,1, 0,1, 0,1, 0,1,2, 0, 0, 0};

// fp16 weights, per-layer row-major [n][Kpad] (zero-padded)
__device__ __align__(16) __half g_wh[WH_TOTAL];

// ----------------------------------------------------------------------------
__device__ __forceinline__ uint32_t smem_u32_of(const void* p) {
    uint32_t a;
    asm("{ .reg .u64 t; cvta.to.shared.u64 t, %1; cvt.u32.u64 %0, t; }" : "=r"(a) : "l"(p));
    return a;
}
__device__ __forceinline__ void cp_async16(uint32_t dst, const void* src) {
    asm volatile("cp.async.cg.shared.global [%0], [%1], 16;" :: "r"(dst), "l"(src));
}
__device__ __forceinline__ void cp_commit() { asm volatile("cp.async.commit_group;"); }
template <int N> __device__ __forceinline__ void cp_wait() {
    asm volatile("cp.async.wait_group %0;" :: "n"(N));
}
__device__ __forceinline__ void ldsm_x4(uint32_t r[4], uint32_t addr) {
    asm volatile("ldmatrix.sync.aligned.m8n8.x4.shared.b16 {%0,%1,%2,%3}, [%4];"
                 : "=r"(r[0]), "=r"(r[1]), "=r"(r[2]), "=r"(r[3]) : "r"(addr));
}
__device__ __forceinline__ void stsm_x2(uint32_t addr, uint32_t r0, uint32_t r1) {
    asm volatile("stmatrix.sync.aligned.m8n8.x2.shared.b16 [%0], {%1,%2};"
                 :: "r"(addr), "r"(r0), "r"(r1) : "memory");
}
__device__ __forceinline__ void mma_f16(float c[4], uint32_t a0, uint32_t a1,
                                        uint32_t a2, uint32_t a3,
                                        uint32_t b0, uint32_t b1) {
    asm volatile(
        "mma.sync.aligned.m16n8k16.row.col.f32.f16.f16.f32 "
        "{%0,%1,%2,%3}, {%4,%5,%6,%7}, {%8,%9}, {%0,%1,%2,%3};"
        : "+f"(c[0]), "+f"(c[1]), "+f"(c[2]), "+f"(c[3])
        : "r"(a0), "r"(a1), "r"(a2), "r"(a3), "r"(b0), "r"(b1));
}
__device__ __forceinline__ void sts128(uint32_t addr, uint32_t a, uint32_t b,
                                       uint32_t c, uint32_t d) {
    asm volatile("st.shared.v4.b32 [%0], {%1,%2,%3,%4};"
                 :: "r"(addr), "r"(a), "r"(b), "r"(c), "r"(d));
}
__device__ __forceinline__ uint4 lds128(uint32_t addr) {
    uint4 u;
    asm volatile("ld.shared.v4.b32 {%0,%1,%2,%3}, [%4];"
                 : "=r"(u.x), "=r"(u.y), "=r"(u.z), "=r"(u.w) : "r"(addr));
    return u;
}
__device__ __forceinline__ uint32_t h2u(__half2 h) { return *(uint32_t*)&h; }

// ============================================================================
// Prepass: fp32 weights -> fp16, zero-padded, per-layer [n][Kpad] row-major
// ============================================================================
__global__ void wconv_kernel(Params P) {
    int i = blockIdx.x * blockDim.x + threadIdx.x;
    if (i >= WH_TOTAL) return;
    int li = 0;
#pragma unroll
    for (int l = 1; l < 13; l++) if (i >= c_woff[l]) li = l;
    int e = i - c_woff[li];
    int Kp = c_kpad[li];
    int n = e / Kp;
    int k = e - n * Kp;
    int Kact = c_kact[li];
    float v = (k < Kact) ? __ldg(P.p[c_widx[li]] + (size_t)n * Kact + k) : 0.0f;
    g_wh[i] = __float2half_rn(v);
}

// ============================================================================
// Weight chunk issue: slice of layer li into ring slot.
// Slot layout: row n = 256B, 16B granules XOR-swizzled by (n&7).
// ============================================================================
__device__ __forceinline__ void issue_chunk(int idx, uint32_t slot, int tid) {
    const int li = ck_li[idx], c = ck_c[idx];
    const int N = (li < 9) ? 256 : 128;
    const int Kp = c_kpad[li];
    const int KS = (li == 0 || ((li == 5 || li == 9) && c == 2)) ? 4 : 8;
    const int ks2 = 2 * KS;                 // granules per row
    const __half* __restrict__ base = g_wh + c_woff[li] + c * 128;
    const int tot = N * ks2;
    const int sh = (KS == 8) ? 4 : 3;
    const int msk = ks2 - 1;
    for (int f = tid; f < tot; f += NTHREADS) {
        int n = f >> sh, g = f & msk;
        cp_async16(slot + (uint32_t)(n * 256 + ((g ^ (n & 7)) << 4)),
                   base + (size_t)n * Kp + g * 8);
    }
    cp_commit();
}

// ============================================================================
// Compute one chunk: KS k-steps of 16. Warp (wm, wn): rows [wm*64,+64),
// cols [wn*NT*8, +NT*8). XBSRC: A from XB (256B rows), else ACT (512B rows).
// ============================================================================
template <int NT, int KS, bool XBSRC>
__device__ __forceinline__ void compute_chunk(float acc[4][8][4], uint32_t abase, int cb,
                                              uint32_t wb, int lane, int wm, int wn) {
    const int arow = lane & 15;
    const int asel = lane >> 4;
    const int brow = lane & 7;
    const int bsel = (lane >> 3) & 1;
    const int bnto = lane >> 4;
    const int RS = XBSRC ? 256 : 512;
    const uint32_t a_base = abase + (uint32_t)((wm * 64 + arow) * RS);
    const int sA = arow & 7;
    const int cbb = (cb >> 3) + asel;
#pragma unroll
    for (int ks = 0; ks < KS; ks++) {
        uint32_t b0[NT], b1[NT];
#pragma unroll
        for (int p = 0; p < NT / 2; p++) {
            int n = wn * (NT * 8) + (2 * p + bnto) * 8 + brow;
            int gr = ks * 2 + bsel;
            uint32_t q[4];
            ldsm_x4(q, wb + (uint32_t)(n * 256 + ((gr ^ brow) << 4)));
            b0[2 * p] = q[0]; b1[2 * p] = q[1];
            b0[2 * p + 1] = q[2]; b1[2 * p + 1] = q[3];
        }
#pragma unroll
        for (int mt = 0; mt < 4; mt++) {
            uint32_t a[4];
            int gr = cbb + ks * 2;
            ldsm_x4(a, a_base + (uint32_t)(mt * 16 * RS + ((gr ^ sA) << 4)));
#pragma unroll
            for (int nt = 0; nt < NT; nt++)
                mma_f16(acc[mt][nt], a[0], a[1], a[2], a[3], b0[nt], b1[nt]);
        }
    }
}

template <int NT>
__device__ __forceinline__ void zero_acc(float acc[4][8][4]) {
#pragma unroll
    for (int m = 0; m < 4; m++)
#pragma unroll
        for (int n = 0; n < NT; n++)
#pragma unroll
            for (int q = 0; q < 4; q++) acc[m][n][q] = 0.0f;
}

// Epilogue: bias (fp32) + cvt to half2 + (relu via hmax2), stmatrix.x2 to ACT.
// D-fragment layout == stmatrix register layout: r0 -> rows base..+7 (c0,c1),
// r1 -> rows base+8..+15 (c2,c3). Lanes 0..15 supply the 16 row addresses.
template <int NT>
__device__ __forceinline__ void epilogue(float acc[4][8][4], uint32_t act_u,
                                         const float* __restrict__ bb, bool relu,
                                         int lane, int wm, int wn) {
    const __half2 z2 = __floats2half2_rn(0.0f, 0.0f);
    const int L = lane & 15;
    const int rx = L & 7;
#pragma unroll
    for (int mt = 0; mt < 4; mt++) {
        const int row = wm * 64 + mt * 16 + L;
        const uint32_t rbase = act_u + (uint32_t)(row * 512);
#pragma unroll
        for (int nt = 0; nt < NT; nt++) {
            int col0 = wn * (NT * 8) + nt * 8 + 2 * (lane & 3);
            float2 bv = __ldg((const float2*)(bb + col0));
            __half2 h0 = __floats2half2_rn(acc[mt][nt][0] + bv.x,
                                           acc[mt][nt][1] + bv.y);
            __half2 h1 = __floats2half2_rn(acc[mt][nt][2] + bv.x,
                                           acc[mt][nt][3] + bv.y);
            if (relu) { h0 = __hmax2(h0, z2); h1 = __hmax2(h1, z2); }
            int g = wn * NT + nt;
            stsm_x2(rbase + (uint32_t)((g ^ rx) << 4), h2u(h0), h2u(h1));
        }
    }
}

// Stage one row of x for tile t into XB (fp16, swizzled): cols 0..62, pad 0.
__device__ __forceinline__ void stage_x_row(const float* __restrict__ xin,
                                            uint32_t xb_u, int t, int r) {
    const float* xr = xin + ((size_t)t * MTILE + r) * 63;
#pragma unroll
    for (int g = 0; g < 16; g++) {
        uint32_t u[4];
#pragma unroll
        for (int q = 0; q < 4; q++) {
            int c = g * 8 + q * 2;
            float f0 = (c < 63) ? __ldg(xr + c) : 0.0f;
            float f1 = (c + 1 < 63) ? __ldg(xr + c + 1) : 0.0f;
            u[q] = h2u(__floats2half2_rn(f0, f1));
        }
        sts128(xb_u + (uint32_t)(r * 256 + ((g ^ (r & 7)) << 4)),
               u[0], u[1], u[2], u[3]);
    }
}

// ============================================================================
// Kernel
// ============================================================================
__global__ void __launch_bounds__(NTHREADS, 1)
nerf_fused_fp16(Params P, float* __restrict__ out, int ntiles, int Btot) {
    extern __shared__ __align__(1024) char sm[];
    const uint32_t sb = smem_u32_of(sm);
    const uint32_t act_u = sb + ACT_OFF;
    const uint32_t xb_u  = sb + XB_OFF;
    const uint32_t wb_u  = sb + WB_OFF;

    const int tid = threadIdx.x;
    const int lane = tid & 31;
    const int w = tid >> 5;
    const int wm = w >> 2;
    const int wn = w & 3;

    const float* __restrict__ xin  = P.p[0];
    const float* __restrict__ ddir = P.p[1];
    const float* __restrict__ wsig = P.p[18];
    const float  bsig = __ldg(P.p[19]);
    const float* __restrict__ wrgb = P.p[30];
    const float* __restrict__ brgb = P.p[31];

    float acc[4][8][4];

    for (int tile = blockIdx.x; tile < ntiles; tile += gridDim.x) {
        // ---- prologue: issue chunk 0 into slot 0
        issue_chunk(0, wb_u, tid);

        // ---- first tile only: stage x (later tiles prefetched at li==12)
        if (tile == (int)blockIdx.x) {
            stage_x_row(xin, xb_u, tile, tid >> 1);   // 2 threads/row (dup ok)
        }
        // chunk-0 barrier below orders XB writes before any reads.

        int gc = 0;
        for (int li = 0; li < 13; li++) {
            const int nch = c_nch[li];
            const bool n256 = (li < 9);
            const float* __restrict__ bb = P.p[c_widx[li] + 1];

            if (n256) zero_acc<8>(acc); else zero_acc<4>(acc);

            for (int c = 0; c < nch; c++) {
                cp_wait<0>();      // this chunk's data arrived (per-thread)
                __syncthreads();   // visible to all; all warps done w/ gc-1;
                                   // also orders prior epilogue/stage writes

                if (gc + 1 < NCHUNKS)
                    issue_chunk(gc + 1, wb_u + ((gc + 1) & 1) * WB_BYTES, tid);

                const uint32_t wb = wb_u + (gc & 1) * WB_BYTES;
                if (li == 0)
                    compute_chunk<8, 4, true >(acc, xb_u, 0, wb, lane, wm, wn);
                else if (li == 5 && c == 2)
                    compute_chunk<8, 4, true >(acc, xb_u, 0, wb, lane, wm, wn);
                else if (li == 9 && c == 2)
                    compute_chunk<4, 4, true >(acc, xb_u, 0, wb, lane, wm, wn);
                else if (n256)
                    compute_chunk<8, 8, false>(acc, act_u, c * 128, wb, lane, wm, wn);
                else
                    compute_chunk<4, 8, false>(acc, act_u, c * 128, wb, lane, wm, wn);
                gc++;
            }

            __syncthreads();   // all warps' reads of ACT/XB this layer done (WAR)
            if (n256) epilogue<8>(acc, act_u, bb, li != 8, lane, wm, wn);
            else      epilogue<4>(acc, act_u, bb, li != 8, lane, wm, wn);
            // No post-epilogue barrier: next layer's chunk-0 cp_wait+sync
            // orders epilogue writes before ACT reads.

            if (li == 5) {
                // d -> XB (x is dead): cols 0..26 = d, rest 0.
                // Safe: pre-epilogue barrier above ended the XB reads.
                int r = tid >> 1, sel = tid & 1;
                const float* dr = ddir + ((size_t)tile * MTILE + r) * 27;
#pragma unroll
                for (int gi = 0; gi < 8; gi++) {
                    int g = sel * 8 + gi;
                    int c0 = g * 8;
                    uint32_t u[4];
#pragma unroll
                    for (int q = 0; q < 4; q++) {
                        int c = c0 + q * 2;
                        float f0 = (c < 27) ? __ldg(dr + c) : 0.0f;
                        float f1 = (c + 1 < 27) ? __ldg(dr + c + 1) : 0.0f;
                        u[q] = h2u(__floats2half2_rn(f0, f1));
                    }
                    sts128(xb_u + (uint32_t)(r * 256 + ((g ^ (r & 7)) << 4)),
                           u[0], u[1], u[2], u[3]);
                }
            }

            if (li == 7) {
                __syncthreads();   // epilogue visible for head
                // sigma = softplus(h7 . wsig + bsig); 2 threads/row
                int r = tid >> 1, sel = tid & 1;
                float a = 0.0f;
#pragma unroll
                for (int i = 0; i < 16; i++) {
                    int g = sel * 16 + i;
                    uint4 u = lds128(act_u + (uint32_t)(r * 512 + ((g ^ (r & 7)) << 4)));
                    __half2* hp = (__half2*)&u;
                    float4 w0 = __ldg((const float4*)(wsig + sel * 128 + i * 8));
                    float4 w1 = __ldg((const float4*)(wsig + sel * 128 + i * 8 + 4));
                    float2 f;
                    f = __half22float2(hp[0]); a += f.x * w0.x + f.y * w0.y;
                    f = __half22float2(hp[1]); a += f.x * w0.z + f.y * w0.w;
                    f = __half22float2(hp[2]); a += f.x * w1.x + f.y * w1.y;
                    f = __half22float2(hp[3]); a += f.x * w1.z + f.y * w1.w;
                }
                a += __shfl_xor_sync(0xFFFFFFFFu, a, 1);
                if (!sel) {
                    float z = a + bsig;
                    float sp = fmaxf(z, 0.0f) + log1pf(expf(-fabsf(z)));
                    out[(size_t)3 * Btot + (size_t)tile * MTILE + r] = sp;
                }
            }
            if (li == 12) {
                __syncthreads();   // epilogue visible for head
                if (tid < MTILE) {
                    // rgb = sigmoid(h12 @ Wrgb^T + brgb)
                    int r = tid;
                    float a0 = 0.0f, a1 = 0.0f, a2 = 0.0f;
#pragma unroll
                    for (int i = 0; i < 16; i++) {
                        uint4 u = lds128(act_u + (uint32_t)(r * 512 + ((i ^ (r & 7)) << 4)));
                        __half2* hp = (__half2*)&u;
                        float4 wa0 = __ldg((const float4*)(wrgb + i * 8));
                        float4 wa1 = __ldg((const float4*)(wrgb + i * 8 + 4));
                        float4 wb0 = __ldg((const float4*)(wrgb + 128 + i * 8));
                        float4 wb1 = __ldg((const float4*)(wrgb + 128 + i * 8 + 4));
                        float4 wc0 = __ldg((const float4*)(wrgb + 256 + i * 8));
                        float4 wc1 = __ldg((const float4*)(wrgb + 256 + i * 8 + 4));
                        float2 f0 = __half22float2(hp[0]);
                        float2 f1 = __half22float2(hp[1]);
                        float2 f2 = __half22float2(hp[2]);
                        float2 f3 = __half22float2(hp[3]);
                        a0 += f0.x*wa0.x + f0.y*wa0.y + f1.x*wa0.z + f1.y*wa0.w
                            + f2.x*wa1.x + f2.y*wa1.y + f3.x*wa1.z + f3.y*wa1.w;
                        a1 += f0.x*wb0.x + f0.y*wb0.y + f1.x*wb0.z + f1.y*wb0.w
                            + f2.x*wb1.x + f2.y*wb1.y + f3.x*wb1.z + f3.y*wb1.w;
                        a2 += f0.x*wc0.x + f0.y*wc0.y + f1.x*wc0.z + f1.y*wc0.w
                            + f2.x*wc1.x + f2.y*wc1.y + f3.x*wc1.z + f3.y*wc1.w;
                    }
                    a0 = 1.0f / (1.0f + expf(-(a0 + __ldg(brgb + 0))));
                    a1 = 1.0f / (1.0f + expf(-(a1 + __ldg(brgb + 1))));
                    a2 = 1.0f / (1.0f + expf(-(a2 + __ldg(brgb + 2))));
                    float* orow = out + ((size_t)tile * MTILE + r) * 3;
                    orow[0] = a0; orow[1] = a1; orow[2] = a2;
                } else {
                    // idle upper warps: prefetch next tile's x into XB
                    // (XB dead since layer 9; next read is next tile's layer-0
                    //  chunk 0, ordered by its chunk-0 barrier)
                    int nt2 = tile + gridDim.x;
                    if (nt2 < ntiles) stage_x_row(xin, xb_u, nt2, tid - MTILE);
                }
            }
        }
    }
}

// ----------------------------------------------------------------------------
extern "C" void kernel_launch(void* const* d_in, const int* in_sizes, int n_in,
                              void* d_out, int out_size) {
    Params P;
    for (int i = 0; i < 32; i++) P.p[i] = (const float*)d_in[i];

    const int B = in_sizes[0] / 63;     // x is [B, 63]
    const int ntiles = B / MTILE;

    // prepass: weights -> fp16 padded row-major layout
    wconv_kernel<<<(WH_TOTAL + 255) / 256, 256>>>(P);

    cudaFuncSetAttribute(nerf_fused_fp16,
                         cudaFuncAttributeMaxDynamicSharedMemorySize, SMEM_TOTAL);

    int nsm = 148;
    cudaDeviceGetAttribute(&nsm, cudaDevAttrMultiProcessorCount, 0);
    int grid = (nsm < ntiles) ? nsm : ntiles;

    nerf_fused_fp16<<<grid, NTHREADS, SMEM_TOTAL>>>(P, (float*)d_out, ntiles, B);
}

// round 17
// speedup vs baseline: 1.0365x; 1.0365x over previous
#include <cuda_runtime.h>
#include <cuda_fp16.h>
#include <cstdint>
#include <math.h>

// ============================================================================
// Fused NeRF MLP (RadianceField), base sm_100 target (no tcgen05).
// fp16 mma.sync.m16n8k16 (fp32 accum) + ldmatrix.x4, persistent 256-thread
// CTAs, weights pre-converted to fp16 and streamed in 128-k chunks through a
// 2-slot cp.async ring (lookahead 1), fp16 activations in SMEM.
// R17: sigma/rgb heads computed from accumulators (no ACT re-read); layer-12
// epilogue removed; next-tile x prefetched by idle threads during rgb final.
// ============================================================================

#define NTHREADS 256
#define MTILE    128

// SMEM map (bytes)
#define ACT_OFF  0                     // 128 rows x 512B (256 half cols), swizzled
#define XB_OFF   65536                 // 128 rows x 256B (128 half cols), swizzled
#define WB_OFF   98304                 // 2 x 65536 weight chunk ring
#define WB_BYTES 65536                 // slot: 256 rows x 256B
#define SSCR_OFF (WB_OFF + 2 * WB_BYTES)     // 229376: sigma scratch 128x4 fp32
#define SMEM_TOTAL (SSCR_OFF + 2048)   // 231424 <= 232448 cap

#define NCHUNKS  24
#define WH_TOTAL 647168

struct Params { const float* p[32]; };

__constant__ int c_widx[13] = {2, 4, 6, 8, 10, 12, 14, 16, 20, 22, 24, 26, 28};
__constant__ int c_kact[13] = {63, 256, 256, 256, 256, 319, 256, 256, 256, 283, 128, 128, 128};
__constant__ int c_kpad[13] = {64, 256, 256, 256, 256, 320, 256, 256, 256, 320, 128, 128, 128};
__constant__ int c_nch [13] = { 1,   2,   2,   2,   2,   3,   2,   2,   2,   3,   1,   1,   1};
__constant__ int c_woff[13] = {0, 16384, 81920, 147456, 212992, 278528, 360448,
                               425984, 491520, 557056, 598016, 614400, 630784};
// flat chunk tables
__constant__ int ck_li[NCHUNKS] = {0, 1,1, 2,2, 3,3, 4,4, 5,5,5, 6,6, 7,7, 8,8, 9,9,9, 10, 11, 12};
__constant__ int ck_c [NCHUNKS] = {0, 0,1, 0,1, 0,1, 0,1, 0,1,2, 0,1, 0,1, 0,1, 0,1,2, 0, 0, 0};

// fp16 weights, per-layer row-major [n][Kpad] (zero-padded)
__device__ __align__(16) __half g_wh[WH_TOTAL];

// ----------------------------------------------------------------------------
__device__ __forceinline__ uint32_t smem_u32_of(const void* p) {
    uint32_t a;
    asm("{ .reg .u64 t; cvta.to.shared.u64 t, %1; cvt.u32.u64 %0, t; }" : "=r"(a) : "l"(p));
    return a;
}
__device__ __forceinline__ void cp_async16(uint32_t dst, const void* src) {
    asm volatile("cp.async.cg.shared.global [%0], [%1], 16;" :: "r"(dst), "l"(src));
}
__device__ __forceinline__ void cp_commit() { asm volatile("cp.async.commit_group;"); }
template <int N> __device__ __forceinline__ void cp_wait() {
    asm volatile("cp.async.wait_group %0;" :: "n"(N));
}
__device__ __forceinline__ void ldsm_x4(uint32_t r[4], uint32_t addr) {
    asm volatile("ldmatrix.sync.aligned.m8n8.x4.shared.b16 {%0,%1,%2,%3}, [%4];"
                 : "=r"(r[0]), "=r"(r[1]), "=r"(r[2]), "=r"(r[3]) : "r"(addr));
}
__device__ __forceinline__ void mma_f16(float c[4], uint32_t a0, uint32_t a1,
                                        uint32_t a2, uint32_t a3,
                                        uint32_t b0, uint32_t b1) {
    asm volatile(
        "mma.sync.aligned.m16n8k16.row.col.f32.f16.f16.f32 "
        "{%0,%1,%2,%3}, {%4,%5,%6,%7}, {%8,%9}, {%0,%1,%2,%3};"
        : "+f"(c[0]), "+f"(c[1]), "+f"(c[2]), "+f"(c[3])
        : "r"(a0), "r"(a1), "r"(a2), "r"(a3), "r"(b0), "r"(b1));
}
__device__ __forceinline__ void sts32(uint32_t addr, uint32_t v) {
    asm volatile("st.shared.b32 [%0], %1;" :: "r"(addr), "r"(v));
}
__device__ __forceinline__ void sts128(uint32_t addr, uint32_t a, uint32_t b,
                                       uint32_t c, uint32_t d) {
    asm volatile("st.shared.v4.b32 [%0], {%1,%2,%3,%4};"
                 :: "r"(addr), "r"(a), "r"(b), "r"(c), "r"(d));
}
__device__ __forceinline__ void stsf(uint32_t addr, float v) {
    asm volatile("st.shared.f32 [%0], %1;" :: "r"(addr), "f"(v));
}
__device__ __forceinline__ float ldsf(uint32_t addr) {
    float f;
    asm volatile("ld.shared.f32 %0, [%1];" : "=f"(f) : "r"(addr));
    return f;
}
__device__ __forceinline__ uint32_t h2u(__half2 h) { return *(uint32_t*)&h; }

// ============================================================================
// Prepass: fp32 weights -> fp16, zero-padded, per-layer [n][Kpad] row-major
// ============================================================================
__global__ void wconv_kernel(Params P) {
    int i = blockIdx.x * blockDim.x + threadIdx.x;
    if (i >= WH_TOTAL) return;
    int li = 0;
#pragma unroll
    for (int l = 1; l < 13; l++) if (i >= c_woff[l]) li = l;
    int e = i - c_woff[li];
    int Kp = c_kpad[li];
    int n = e / Kp;
    int k = e - n * Kp;
    int Kact = c_kact[li];
    float v = (k < Kact) ? __ldg(P.p[c_widx[li]] + (size_t)n * Kact + k) : 0.0f;
    g_wh[i] = __float2half_rn(v);
}

// ============================================================================
// Weight chunk issue: slice of layer li into ring slot.
// Slot layout: row n = 256B, 16B granules XOR-swizzled by (n&7).
// ============================================================================
__device__ __forceinline__ void issue_chunk(int idx, uint32_t slot, int tid) {
    const int li = ck_li[idx], c = ck_c[idx];
    const int N = (li < 9) ? 256 : 128;
    const int Kp = c_kpad[li];
    const int KS = (li == 0 || ((li == 5 || li == 9) && c == 2)) ? 4 : 8;
    const int ks2 = 2 * KS;                 // granules per row
    const __half* __restrict__ base = g_wh + c_woff[li] + c * 128;
    const int tot = N * ks2;
    const int sh = (KS == 8) ? 4 : 3;
    const int msk = ks2 - 1;
    for (int f = tid; f < tot; f += NTHREADS) {
        int n = f >> sh, g = f & msk;
        cp_async16(slot + (uint32_t)(n * 256 + ((g ^ (n & 7)) << 4)),
                   base + (size_t)n * Kp + g * 8);
    }
    cp_commit();
}

// ============================================================================
// Compute one chunk: KS k-steps of 16. Warp (wm, wn): rows [wm*64,+64),
// cols [wn*NT*8, +NT*8). XBSRC: A from XB (256B rows), else ACT (512B rows).
// ============================================================================
template <int NT, int KS, bool XBSRC>
__device__ __forceinline__ void compute_chunk(float acc[4][8][4], uint32_t abase, int cb,
                                              uint32_t wb, int lane, int wm, int wn) {
    const int arow = lane & 15;
    const int asel = lane >> 4;
    const int brow = lane & 7;
    const int bsel = (lane >> 3) & 1;
    const int bnto = lane >> 4;
    const int RS = XBSRC ? 256 : 512;
    const uint32_t a_base = abase + (uint32_t)((wm * 64 + arow) * RS);
    const int sA = arow & 7;
    const int cbb = (cb >> 3) + asel;
#pragma unroll
    for (int ks = 0; ks < KS; ks++) {
        uint32_t b0[NT], b1[NT];
#pragma unroll
        for (int p = 0; p < NT / 2; p++) {
            int n = wn * (NT * 8) + (2 * p + bnto) * 8 + brow;
            int gr = ks * 2 + bsel;
            uint32_t q[4];
            ldsm_x4(q, wb + (uint32_t)(n * 256 + ((gr ^ brow) << 4)));
            b0[2 * p] = q[0]; b1[2 * p] = q[1];
            b0[2 * p + 1] = q[2]; b1[2 * p + 1] = q[3];
        }
#pragma unroll
        for (int mt = 0; mt < 4; mt++) {
            uint32_t a[4];
            int gr = cbb + ks * 2;
            ldsm_x4(a, a_base + (uint32_t)(mt * 16 * RS + ((gr ^ sA) << 4)));
#pragma unroll
            for (int nt = 0; nt < NT; nt++)
                mma_f16(acc[mt][nt], a[0], a[1], a[2], a[3], b0[nt], b1[nt]);
        }
    }
}

template <int NT>
__device__ __forceinline__ void zero_acc(float acc[4][8][4]) {
#pragma unroll
    for (int m = 0; m < 4; m++)
#pragma unroll
        for (int n = 0; n < NT; n++)
#pragma unroll
            for (int q = 0; q < 4; q++) acc[m][n][q] = 0.0f;
}

// Epilogue: bias (fp32) + cvt to half2 + (relu via hmax2), write to ACT.
template <int NT>
__device__ __forceinline__ void epilogue(float acc[4][8][4], uint32_t act_u,
                                         const float* __restrict__ bb, bool relu,
                                         int lane, int wm, int wn) {
    const __half2 z2 = __floats2half2_rn(0.0f, 0.0f);
#pragma unroll
    for (int mt = 0; mt < 4; mt++) {
        int row0 = wm * 64 + mt * 16 + (lane >> 2);
        int row1 = row0 + 8;
#pragma unroll
        for (int nt = 0; nt < NT; nt++) {
            int col0 = wn * (NT * 8) + nt * 8 + 2 * (lane & 3);
            float2 bv = __ldg((const float2*)(bb + col0));
            __half2 h0 = __floats2half2_rn(acc[mt][nt][0] + bv.x,
                                           acc[mt][nt][1] + bv.y);
            __half2 h1 = __floats2half2_rn(acc[mt][nt][2] + bv.x,
                                           acc[mt][nt][3] + bv.y);
            if (relu) { h0 = __hmax2(h0, z2); h1 = __hmax2(h1, z2); }
            int g = col0 >> 3, cb2 = (col0 & 7) * 2;
            sts32(act_u + (uint32_t)(row0 * 512 + ((g ^ (row0 & 7)) << 4) + cb2), h2u(h0));
            sts32(act_u + (uint32_t)(row1 * 512 + ((g ^ (row1 & 7)) << 4) + cb2), h2u(h1));
        }
    }
}

// Stage one row of x for tile t into XB (fp16, swizzled): cols 0..62, pad 0.
__device__ __forceinline__ void stage_x_row(const float* __restrict__ xin,
                                            uint32_t xb_u, int t, int r) {
    const float* xr = xin + ((size_t)t * MTILE + r) * 63;
#pragma unroll
    for (int g = 0; g < 16; g++) {
        uint32_t u[4];
#pragma unroll
        for (int q = 0; q < 4; q++) {
            int c = g * 8 + q * 2;
            float f0 = (c < 63) ? __ldg(xr + c) : 0.0f;
            float f1 = (c + 1 < 63) ? __ldg(xr + c + 1) : 0.0f;
            u[q] = h2u(__floats2half2_rn(f0, f1));
        }
        sts128(xb_u + (uint32_t)(r * 256 + ((g ^ (r & 7)) << 4)),
               u[0], u[1], u[2], u[3]);
    }
}

// ============================================================================
// Kernel
// ============================================================================
__global__ void __launch_bounds__(NTHREADS, 1)
nerf_fused_fp16(Params P, float* __restrict__ out, int ntiles, int Btot) {
    extern __shared__ __align__(1024) char sm[];
    const uint32_t sb = smem_u32_of(sm);
    const uint32_t act_u = sb + ACT_OFF;
    const uint32_t xb_u  = sb + XB_OFF;
    const uint32_t wb_u  = sb + WB_OFF;
    const uint32_t sscr  = sb + SSCR_OFF;     // 128 x 4 fp32 sigma partials
    const uint32_t rscr  = wb_u;              // rgb partials in WB slot 0 (dead)

    const int tid = threadIdx.x;
    const int lane = tid & 31;
    const int w = tid >> 5;
    const int wm = w >> 2;
    const int wn = w & 3;

    const float* __restrict__ xin  = P.p[0];
    const float* __restrict__ ddir = P.p[1];
    const float* __restrict__ wsig = P.p[18];
    const float  bsig = __ldg(P.p[19]);
    const float* __restrict__ wrgb = P.p[30];
    const float* __restrict__ brgb = P.p[31];

    float acc[4][8][4];

    for (int tile = blockIdx.x; tile < ntiles; tile += gridDim.x) {
        // ---- prologue: issue chunk 0 into slot 0
        issue_chunk(0, wb_u, tid);

        // ---- first tile only: stage x (later tiles prefetched at li==12)
        if (tile == (int)blockIdx.x) {
            stage_x_row(xin, xb_u, tile, tid >> 1);   // 2 threads/row (dup ok)
        }
        // chunk-0 barrier below orders XB writes before any reads.

        int gc = 0;
        for (int li = 0; li < 13; li++) {
            const int nch = c_nch[li];
            const bool n256 = (li < 9);
            const float* __restrict__ bb = P.p[c_widx[li] + 1];

            if (n256) zero_acc<8>(acc); else zero_acc<4>(acc);

            for (int c = 0; c < nch; c++) {
                cp_wait<0>();      // this chunk's data arrived (per-thread)
                __syncthreads();   // visible to all; all warps done w/ gc-1;
                                   // also orders prior epilogue/stage writes

                if (gc + 1 < NCHUNKS)
                    issue_chunk(gc + 1, wb_u + ((gc + 1) & 1) * WB_BYTES, tid);

                const uint32_t wb = wb_u + (gc & 1) * WB_BYTES;
                if (li == 0)
                    compute_chunk<8, 4, true >(acc, xb_u, 0, wb, lane, wm, wn);
                else if (li == 5 && c == 2)
                    compute_chunk<8, 4, true >(acc, xb_u, 0, wb, lane, wm, wn);
                else if (li == 9 && c == 2)
                    compute_chunk<4, 4, true >(acc, xb_u, 0, wb, lane, wm, wn);
                else if (n256)
                    compute_chunk<8, 8, false>(acc, act_u, c * 128, wb, lane, wm, wn);
                else
                    compute_chunk<4, 8, false>(acc, act_u, c * 128, wb, lane, wm, wn);
                gc++;
            }

            if (li != 12) {
                __syncthreads();   // all warps' reads of ACT/XB done (WAR)
                if (n256) epilogue<8>(acc, act_u, bb, li != 8, lane, wm, wn);
                else      epilogue<4>(acc, act_u, bb, li != 8, lane, wm, wn);
                // No post-epilogue barrier: next layer's chunk-0 cp_wait+sync
                // orders epilogue writes before ACT reads.
            }

            if (li == 5) {
                // d -> XB (x is dead): cols 0..26 = d, rest 0.
                int r = tid >> 1, sel = tid & 1;
                const float* dr = ddir + ((size_t)tile * MTILE + r) * 27;
#pragma unroll
                for (int gi = 0; gi < 8; gi++) {
                    int g = sel * 8 + gi;
                    int c0 = g * 8;
                    uint32_t u[4];
#pragma unroll
                    for (int q = 0; q < 4; q++) {
                        int c = c0 + q * 2;
                        float f0 = (c < 27) ? __ldg(dr + c) : 0.0f;
                        float f1 = (c + 1 < 27) ? __ldg(dr + c + 1) : 0.0f;
                        u[q] = h2u(__floats2half2_rn(f0, f1));
                    }
                    sts128(xb_u + (uint32_t)(r * 256 + ((g ^ (r & 7)) << 4)),
                           u[0], u[1], u[2], u[3]);
                }
            }

            if (li == 7) {
                // sigma partials from accumulators: s[row] = sum relu(acc+b)*wsig
                // (acc intact after epilogue). Quad-reduce, scratch per (row, wn).
#pragma unroll
                for (int mt = 0; mt < 4; mt++) {
                    float s0 = 0.0f, s1 = 0.0f;
#pragma unroll
                    for (int nt = 0; nt < 8; nt++) {
                        int c0 = wn * 64 + nt * 8 + 2 * (lane & 3);
                        float2 bv = __ldg((const float2*)(bb + c0));
                        float2 ws = __ldg((const float2*)(wsig + c0));
                        float v0 = fmaxf(acc[mt][nt][0] + bv.x, 0.0f);
                        float v1 = fmaxf(acc[mt][nt][1] + bv.y, 0.0f);
                        float v2 = fmaxf(acc[mt][nt][2] + bv.x, 0.0f);
                        float v3 = fmaxf(acc[mt][nt][3] + bv.y, 0.0f);
                        s0 += v0 * ws.x + v1 * ws.y;
                        s1 += v2 * ws.x + v3 * ws.y;
                    }
                    s0 += __shfl_xor_sync(0xFFFFFFFFu, s0, 1);
                    s0 += __shfl_xor_sync(0xFFFFFFFFu, s0, 2);
                    s1 += __shfl_xor_sync(0xFFFFFFFFu, s1, 1);
                    s1 += __shfl_xor_sync(0xFFFFFFFFu, s1, 2);
                    if ((lane & 3) == 0) {
                        int r0 = wm * 64 + mt * 16 + (lane >> 2);
                        stsf(sscr + (uint32_t)((r0 * 4 + wn) * 4), s0);
                        stsf(sscr + (uint32_t)(((r0 + 8) * 4 + wn) * 4), s1);
                    }
                }
                __syncthreads();   // scratch + epilogue visible
                if (tid < MTILE) {
                    float a = ldsf(sscr + (uint32_t)(tid * 16))
                            + ldsf(sscr + (uint32_t)(tid * 16 + 4))
                            + ldsf(sscr + (uint32_t)(tid * 16 + 8))
                            + ldsf(sscr + (uint32_t)(tid * 16 + 12));
                    float z = a + bsig;
                    float sp = fmaxf(z, 0.0f) + log1pf(expf(-fabsf(z)));
                    out[(size_t)3 * Btot + (size_t)tile * MTILE + tid] = sp;
                }
            }

            if (li == 12) {
                // rgb partials from accumulators (no epilogue, no pre-barrier:
                // registers only; scratch = WB slot 0, dead since chunk 22).
#pragma unroll
                for (int mt = 0; mt < 4; mt++) {
                    float s00 = 0.0f, s01 = 0.0f, s02 = 0.0f;
                    float s10 = 0.0f, s11 = 0.0f, s12 = 0.0f;
#pragma unroll
                    for (int nt = 0; nt < 4; nt++) {
                        int c0 = wn * 32 + nt * 8 + 2 * (lane & 3);
                        float2 bv = __ldg((const float2*)(bb + c0));
                        float2 w0 = __ldg((const float2*)(wrgb + c0));
                        float2 w1 = __ldg((const float2*)(wrgb + 128 + c0));
                        float2 w2 = __ldg((const float2*)(wrgb + 256 + c0));
                        float v0 = fmaxf(acc[mt][nt][0] + bv.x, 0.0f);
                        float v1 = fmaxf(acc[mt][nt][1] + bv.y, 0.0f);
                        float v2 = fmaxf(acc[mt][nt][2] + bv.x, 0.0f);
                        float v3 = fmaxf(acc[mt][nt][3] + bv.y, 0.0f);
                        s00 += v0 * w0.x + v1 * w0.y;
                        s01 += v0 * w1.x + v1 * w1.y;
                        s02 += v0 * w2.x + v1 * w2.y;
                        s10 += v2 * w0.x + v3 * w0.y;
                        s11 += v2 * w1.x + v3 * w1.y;
                        s12 += v2 * w2.x + v3 * w2.y;
                    }
                    s00 += __shfl_xor_sync(0xFFFFFFFFu, s00, 1);
                    s00 += __shfl_xor_sync(0xFFFFFFFFu, s00, 2);
                    s01 += __shfl_xor_sync(0xFFFFFFFFu, s01, 1);
                    s01 += __shfl_xor_sync(0xFFFFFFFFu, s01, 2);
                    s02 += __shfl_xor_sync(0xFFFFFFFFu, s02, 1);
                    s02 += __shfl_xor_sync(0xFFFFFFFFu, s02, 2);
                    s10 += __shfl_xor_sync(0xFFFFFFFFu, s10, 1);
                    s10 += __shfl_xor_sync(0xFFFFFFFFu, s10, 2);
                    s11 += __shfl_xor_sync(0xFFFFFFFFu, s11, 1);
                    s11 += __shfl_xor_sync(0xFFFFFFFFu, s11, 2);
                    s12 += __shfl_xor_sync(0xFFFFFFFFu, s12, 1);
                    s12 += __shfl_xor_sync(0xFFFFFFFFu, s12, 2);
                    if ((lane & 3) == 0) {
                        int r0 = wm * 64 + mt * 16 + (lane >> 2);
                        uint32_t a0 = rscr + (uint32_t)((r0 * 4 + wn) * 12);
                        stsf(a0, s00); stsf(a0 + 4, s01); stsf(a0 + 8, s02);
                        uint32_t a1 = rscr + (uint32_t)(((r0 + 8) * 4 + wn) * 12);
                        stsf(a1, s10); stsf(a1 + 4, s11); stsf(a1 + 8, s12);
                    }
                }
                __syncthreads();   // rgb scratch visible
                if (tid < MTILE) {
                    int r = tid;
                    float a0 = 0.0f, a1 = 0.0f, a2 = 0.0f;
#pragma unroll
                    for (int j = 0; j < 4; j++) {
                        uint32_t a = rscr + (uint32_t)((r * 4 + j) * 12);
                        a0 += ldsf(a); a1 += ldsf(a + 4); a2 += ldsf(a + 8);
                    }
                    a0 = 1.0f / (1.0f + expf(-(a0 + __ldg(brgb + 0))));
                    a1 = 1.0f / (1.0f + expf(-(a1 + __ldg(brgb + 1))));
                    a2 = 1.0f / (1.0f + expf(-(a2 + __ldg(brgb + 2))));
                    float* orow = out + ((size_t)tile * MTILE + r) * 3;
                    orow[0] = a0; orow[1] = a1; orow[2] = a2;
                } else {
                    // idle upper threads: prefetch next tile's x into XB
                    int nt2 = tile + gridDim.x;
                    if (nt2 < ntiles) stage_x_row(xin, xb_u, nt2, tid - MTILE);
                }
                __syncthreads();   // scratch reads done before next tile's
                                   // chunk-0 cp.async overwrites WB slot 0
            }
        }
    }
}

// ----------------------------------------------------------------------------
extern "C" void kernel_launch(void* const* d_in, const int* in_sizes, int n_in,
                              void* d_out, int out_size) {
    Params P;
    for (int i = 0; i < 32; i++) P.p[i] = (const float*)d_in[i];

    const int B = in_sizes[0] / 63;     // x is [B, 63]
    const int ntiles = B / MTILE;

    // prepass: weights -> fp16 padded row-major layout
    wconv_kernel<<<(WH_TOTAL + 255) / 256, 256>>>(P);

    cudaFuncSetAttribute(nerf_fused_fp16,
                         cudaFuncAttributeMaxDynamicSharedMemorySize, SMEM_TOTAL);

    int nsm = 148;
    cudaDeviceGetAttribute(&nsm, cudaDevAttrMultiProcessorCount, 0);
    int grid = (nsm < ntiles) ? nsm : ntiles;

    nerf_fused_fp16<<<grid, NTHREADS, SMEM_TOTAL>>>(P, (float*)d_out, ntiles, B);
}